// round 5
// baseline (speedup 1.0000x reference)
#include <cuda_runtime.h>
#include <math.h>

#define H 1024
#define L 128
#define V 50257

// ---- scratch (device globals; no allocation allowed) ----
__device__ __align__(16) float g_attn_logits[L];
__device__ __align__(16) float g_attn_w[L];
__device__ __align__(16) float g_with_attn[H];
__device__ __align__(16) float g_rnn_in[H];
__device__ __align__(16) float g_hnew[H];
__device__ __align__(16) float g_logits[V];
__device__ unsigned int g_max_enc;   // ordered-uint encoded max
__device__ float g_sumexp;

__device__ __forceinline__ float warp_sum(float v) {
#pragma unroll
    for (int o = 16; o > 0; o >>= 1) v += __shfl_xor_sync(0xffffffffu, v, o);
    return v;
}

__device__ __forceinline__ float dot4(float4 a, float4 b) {
    return a.x * b.x + a.y * b.y + a.z * b.z + a.w * b.w;
}

// encode float so unsigned compare == float compare
__device__ __forceinline__ unsigned int enc_f(float f) {
    unsigned int u = __float_as_uint(f);
    return (u & 0x80000000u) ? ~u : (u | 0x80000000u);
}
__device__ __forceinline__ float dec_f(unsigned int u) {
    return (u & 0x80000000u) ? __uint_as_float(u ^ 0x80000000u)
                             : __uint_as_float(~u);
}

// ---- K1: attention logits[l] = dot(attn_W[l], [emb[x], h0]) + attn_b[l] ----
__global__ void __launch_bounds__(256) k_attn_logits(const int* __restrict__ x,
                              const float* __restrict__ hidden,
                              const float* __restrict__ emb,
                              const float* __restrict__ attn_W,
                              const float* __restrict__ attn_b) {
    int l = blockIdx.x;          // 0..127
    int t = threadIdx.x;         // 0..255
    const float* erow = emb + (long long)x[0] * H;
    const float* wrow = attn_W + (long long)l * 2 * H;
    int j = t * 4;
    float4 w0 = __ldcs((const float4*)(wrow + j));
    float4 w1 = __ldcs((const float4*)(wrow + H + j));
    float4 c0 = *(const float4*)(erow + j);
    float4 c1 = *(const float4*)(hidden + j);
    float acc = dot4(w0, c0) + dot4(w1, c1);
    acc = warp_sum(acc);
    __shared__ float s[8];
    if ((t & 31) == 0) s[t >> 5] = acc;
    __syncthreads();
    if (t < 8) {
        float v = s[t];
#pragma unroll
        for (int o = 4; o > 0; o >>= 1) v += __shfl_xor_sync(0xffu, v, o);
        if (t == 0) g_attn_logits[l] = v + attn_b[l];
    }
}

// ---- K2: softmax over 128 logits; zero with_attn; reset atomics ----
__global__ void __launch_bounds__(256) k_attn_softmax(float* __restrict__ out_attn) {
    int t = threadIdx.x;  // 0..255
    *(float4*)(g_with_attn + t * 4) = make_float4(0.f, 0.f, 0.f, 0.f);
    if (t >= L) {
        if (t == L) { g_max_enc = 0u; g_sumexp = 0.f; }
        return;
    }
    float v = g_attn_logits[t];
    __shared__ float redm[4], reds[4];
    float m = v;
#pragma unroll
    for (int o = 16; o > 0; o >>= 1) m = fmaxf(m, __shfl_xor_sync(0xffffffffu, m, o));
    if ((t & 31) == 0) redm[t >> 5] = m;
    __syncthreads();
    float m4 = fmaxf(fmaxf(redm[0], redm[1]), fmaxf(redm[2], redm[3]));
    float e = expf(v - m4);
    float s = warp_sum(e);
    if ((t & 31) == 0) reds[t >> 5] = s;
    __syncthreads();
    float tot = reds[0] + reds[1] + reds[2] + reds[3];
    float w = e / tot;
    g_attn_w[t] = w;
    out_attn[t] = w;
}

// ---- K3: with_attn[h] += sum over 32-row chunk of w[l]*enc[l,h] ----
__global__ void __launch_bounds__(256) k_with_attn(const float* __restrict__ enc) {
    int col = blockIdx.x * 256 + threadIdx.x;
    int l0 = blockIdx.y * 32;
    float acc0 = 0.f, acc1 = 0.f, acc2 = 0.f, acc3 = 0.f;
#pragma unroll
    for (int l = l0; l < l0 + 32; l += 4) {
        acc0 += g_attn_w[l + 0] * __ldg(enc + (l + 0) * H + col);
        acc1 += g_attn_w[l + 1] * __ldg(enc + (l + 1) * H + col);
        acc2 += g_attn_w[l + 2] * __ldg(enc + (l + 2) * H + col);
        acc3 += g_attn_w[l + 3] * __ldg(enc + (l + 3) * H + col);
    }
    atomicAdd(&g_with_attn[col], (acc0 + acc1) + (acc2 + acc3));
}

// ---- K4: rnn_in. 2 rows per block, 4 warps per row, 4 batched float4/lane ----
__global__ void __launch_bounds__(256) k_rnn_in(const int* __restrict__ x,
                                                const float* __restrict__ emb,
                                                const float* __restrict__ comb_W,
                                                const float* __restrict__ comb_b) {
    int t = threadIdx.x;                 // 0..255
    int w = t >> 5;                      // warp 0..7
    int lane = t & 31;
    int rsel = w >> 2;                   // 0 or 1: which row of this block
    int wr = w & 3;                      // warp-in-row 0..3 (512 cols each)
    int row = blockIdx.x * 2 + rsel;
    const float* erow = emb + (long long)x[0] * H;
    const float* wrow = comb_W + (long long)row * 2 * H;
    // warp wr covers cols [wr*512, wr*512+512): wr 0,1 -> emb half; 2,3 -> attn half
    const float* cat = (wr < 2) ? (erow + wr * 512) : (g_with_attn + (wr - 2) * 512);
    const float* wp = wrow + wr * 512;
    float4 a[4], c[4];
#pragma unroll
    for (int k = 0; k < 4; k++) a[k] = __ldcs((const float4*)(wp + k * 128 + lane * 4));
#pragma unroll
    for (int k = 0; k < 4; k++) c[k] = *(const float4*)(cat + k * 128 + lane * 4);
    float acc = 0.f;
#pragma unroll
    for (int k = 0; k < 4; k++) acc += dot4(a[k], c[k]);
    acc = warp_sum(acc);
    __shared__ float s[8];
    if (lane == 0) s[w] = acc;
    __syncthreads();
    if (t == 0 || t == 128) {
        int r = blockIdx.x * 2 + (t >> 7);
        const float* sp = s + (t >> 7) * 4;
        float v = (sp[0] + sp[1]) + (sp[2] + sp[3]);
        g_rnn_in[r] = fmaxf(v + comb_b[r], 0.f);
    }
}

// ---- K5: GRU. 2 outputs per block; warp = one full 1024-dot; 8 batched float4 ----
__global__ void __launch_bounds__(384) k_gru(const float* __restrict__ hidden,
                                             const float* __restrict__ W_ih,
                                             const float* __restrict__ W_hh,
                                             const float* __restrict__ b_ih,
                                             const float* __restrict__ b_hh,
                                             float* __restrict__ out_h) {
    int t = threadIdx.x;
    int w = t >> 5;                      // 0..11
    int lane = t & 31;
    int isel = (w >= 6) ? 1 : 0;
    int d = w - isel * 6;                // dot index 0..5
    int i = blockIdx.x * 2 + isel;       // hidden index
    int g = (d < 3) ? d : (d - 3);
    const float* row;
    const float* vec;
    float bias;
    if (d < 3) { row = W_ih + (long long)(g * H + i) * H; vec = g_rnn_in; bias = b_ih[g * H + i]; }
    else       { row = W_hh + (long long)(g * H + i) * H; vec = hidden;  bias = b_hh[g * H + i]; }
    float4 a[8];
#pragma unroll
    for (int k = 0; k < 8; k++) a[k] = __ldcs((const float4*)(row + k * 128 + lane * 4));
    float acc = 0.f;
#pragma unroll
    for (int k = 0; k < 8; k++) {
        float4 b = *(const float4*)(vec + k * 128 + lane * 4);
        acc += dot4(a[k], b);
    }
    acc = warp_sum(acc);
    __shared__ float s[12];
    if (lane == 0) s[w] = acc + bias;
    __syncthreads();
    if (t < 2) {
        int ii = blockIdx.x * 2 + t;
        const float* sp = s + t * 6;
        float r = 1.f / (1.f + expf(-(sp[0] + sp[3])));
        float z = 1.f / (1.f + expf(-(sp[1] + sp[4])));
        float n = tanhf(sp[2] + r * sp[5]);
        float h = (1.f - z) * n + z * hidden[ii];
        g_hnew[ii] = h;
        out_h[ii] = h;
    }
}

// ---- K6: big vocab GEMV. warp per 2 rows; all 16 loads batched for MLP ----
__global__ void __launch_bounds__(256, 2) k_logits(const float* __restrict__ out_W,
                                                   const float* __restrict__ out_b) {
    int lane = threadIdx.x & 31;
    int warp = (blockIdx.x * blockDim.x + threadIdx.x) >> 5;
    int nwarps = (gridDim.x * blockDim.x) >> 5;
    float4 h[8];
#pragma unroll
    for (int k = 0; k < 8; k++)
        h[k] = *(const float4*)(g_hnew + k * 128 + lane * 4);
    float lmax = -INFINITY;
    for (int v0 = warp * 2; v0 < V - 1; v0 += nwarps * 2) {
        const float* row0 = out_W + (long long)v0 * H + lane * 4;
        const float* row1 = row0 + H;
        float4 a0[8], a1[8];
#pragma unroll
        for (int k = 0; k < 8; k++) a0[k] = __ldcs((const float4*)(row0 + k * 128));
#pragma unroll
        for (int k = 0; k < 8; k++) a1[k] = __ldcs((const float4*)(row1 + k * 128));
        float acc0 = 0.f, acc1 = 0.f;
#pragma unroll
        for (int k = 0; k < 8; k++) {
            acc0 += dot4(a0[k], h[k]);
            acc1 += dot4(a1[k], h[k]);
        }
        acc0 = warp_sum(acc0);
        acc1 = warp_sum(acc1);
        if (lane == 0) {
            float lg0 = acc0 + out_b[v0];
            float lg1 = acc1 + out_b[v0 + 1];
            g_logits[v0] = lg0;
            g_logits[v0 + 1] = lg1;
            lmax = fmaxf(lmax, fmaxf(lg0, lg1));
        }
    }
    // tail: last row (V odd) handled by warp 0
    if (warp == 0) {
        int v = V - 1;
        const float* row = out_W + (long long)v * H + lane * 4;
        float acc = 0.f;
#pragma unroll
        for (int k = 0; k < 8; k++)
            acc += dot4(__ldcs((const float4*)(row + k * 128)), h[k]);
        acc = warp_sum(acc);
        if (lane == 0) {
            float lg = acc + out_b[v];
            g_logits[v] = lg;
            lmax = fmaxf(lmax, lg);
        }
    }
    if (lane == 0 && lmax > -INFINITY) {
        atomicMax(&g_max_enc, enc_f(lmax));
    }
}

// ---- K7: sum of exp(logit - max) ----
__global__ void __launch_bounds__(256) k_sumexp() {
    float gmax = dec_f(g_max_enc);
    int idx = blockIdx.x * blockDim.x + threadIdx.x;
    int stride = gridDim.x * blockDim.x;
    float s = 0.f;
    for (int v = idx; v < V; v += stride) s += expf(g_logits[v] - gmax);
    s = warp_sum(s);
    __shared__ float red[8];
    if ((threadIdx.x & 31) == 0) red[threadIdx.x >> 5] = s;
    __syncthreads();
    if (threadIdx.x == 0) {
        float t = 0.f;
#pragma unroll
        for (int i = 0; i < 8; i++) t += red[i];
        atomicAdd(&g_sumexp, t);
    }
}

// ---- K8: logp[v] = logit[v] - (max + log(sumexp)) ----
__global__ void __launch_bounds__(256) k_writeout(float* __restrict__ out) {
    float gmax = dec_f(g_max_enc);
    float lse = gmax + logf(g_sumexp);
    int idx = blockIdx.x * blockDim.x + threadIdx.x;
    int stride = gridDim.x * blockDim.x;
    for (int v = idx; v < V; v += stride) out[v] = g_logits[v] - lse;
}

extern "C" void kernel_launch(void* const* d_in, const int* in_sizes, int n_in,
                              void* d_out, int out_size) {
    const int*   x       = (const int*)d_in[0];
    const float* hidden  = (const float*)d_in[1];
    const float* enc     = (const float*)d_in[2];
    const float* emb     = (const float*)d_in[3];
    const float* attn_W  = (const float*)d_in[4];
    const float* attn_b  = (const float*)d_in[5];
    const float* comb_W  = (const float*)d_in[6];
    const float* comb_b  = (const float*)d_in[7];
    const float* W_ih    = (const float*)d_in[8];
    const float* W_hh    = (const float*)d_in[9];
    const float* b_ih    = (const float*)d_in[10];
    const float* b_hh    = (const float*)d_in[11];
    const float* out_W   = (const float*)d_in[12];
    const float* out_b   = (const float*)d_in[13];
    float* out = (float*)d_out;   // layout: [logp V][h_new H][attn_w L]

    k_attn_logits<<<L, 256>>>(x, hidden, emb, attn_W, attn_b);
    k_attn_softmax<<<1, 256>>>(out + V + H);
    {
        dim3 g(H / 256, 4);
        k_with_attn<<<g, 256>>>(enc);
    }
    k_rnn_in<<<H / 2, 256>>>(x, emb, comb_W, comb_b);
    k_gru<<<H / 2, 384>>>(hidden, W_ih, W_hh, b_ih, b_hh, out + V);
    k_logits<<<296, 256>>>(out_W, out_b);   // 2 blocks/SM on 148 SMs
    k_sumexp<<<256, 256>>>();
    k_writeout<<<256, 256>>>(out);
}